// round 5
// baseline (speedup 1.0000x reference)
#include <cuda_runtime.h>
#include <cstdint>

typedef unsigned long long ull;

#define BATCH 4
#define NPTS  8192
#define RT    64           // rows (pred points) per block
#define RPW   4            // rows per warp (16 warps)
#define CG    512          // cols (gt points) per block
#define NRT   (NPTS/RT)    // 128 row tiles
#define NCG   (NPTS/CG)    // 16 col groups
#define NPASS (CG/64)      // 8 passes (64 cols per pass, 2 per lane)

// Scratch (disjoint writers -> no init, no atomics, deterministic)
__device__ float g_rpart[NCG * BATCH * NPTS];   // [cg][b][n]  2 MB
__device__ float g_cpart[NRT * BATCH * NPTS];   // [rt][b][m] 16 MB
__device__ float g_pr[128], g_pc[128];

// ---- packed f32x2 helpers (sm_100+) ----
__device__ __forceinline__ ull pk2(float lo, float hi) {
    ull r; asm("mov.b64 %0, {%1, %2};" : "=l"(r) : "f"(lo), "f"(hi)); return r;
}
__device__ __forceinline__ void upk2(ull v, float& lo, float& hi) {
    asm("mov.b64 {%0, %1}, %2;" : "=f"(lo), "=f"(hi) : "l"(v));
}
__device__ __forceinline__ ull ffma2(ull a, ull b, ull c) {
    ull d; asm("fma.rn.f32x2 %0, %1, %2, %3;" : "=l"(d) : "l"(a), "l"(b), "l"(c)); return d;
}
__device__ __forceinline__ ull fadd2(ull a, ull b) {
    ull d; asm("add.rn.f32x2 %0, %1, %2;" : "=l"(d) : "l"(a), "l"(b)); return d;
}

// ============================================================================
// Warp-owns-rows fused kernel. Block = (cg, rt, b); 16 warps x 32 lanes.
// Warp w owns rows [w*4, w*4+4); lane owns col pair (pass*64 + lane*2).
// dist = ||p||^2 + ||g||^2 - 2 p.g:
//   s = fma(-2py, gy, fma(-2px, gx, g2))     (g2 folded: col constant)
//   row-min accumulates s in lo/hi halves (x2, a row constant, added at end)
//   d = s + x2 (FADD2); col-min accumulates d in lo/hi halves
// 7 instrs per 2 pairs (3 fma-pipe + 4 alu-pipe). Two barriers per block.
// ============================================================================
__global__ __launch_bounds__(512, 2) void chamfer_tile(const float* __restrict__ pred,
                                                       const float* __restrict__ gt) {
    const int cg = blockIdx.x, rt = blockIdx.y, b = blockIdx.z;
    const int tid = threadIdx.x;
    const int w = tid >> 5, lane = tid & 31;

    __shared__ __align__(16) float s_gx[CG], s_gy[CG], s_g2[CG];
    __shared__ __align__(16) float s_px2[RT], s_py2[RT], s_x2[RT];
    __shared__ __align__(16) float s_colpart[16][CG];

    // Vectorized loads; derived quantities computed inline
    {
        float2 v = ((const float2*)gt)[(size_t)b * NPTS + (size_t)cg * CG + tid];
        s_gx[tid] = v.x; s_gy[tid] = v.y; s_g2[tid] = v.x * v.x + v.y * v.y;
    }
    if (tid < RT) {
        float2 p = ((const float2*)pred)[(size_t)b * NPTS + (size_t)rt * RT + tid];
        s_px2[tid] = -2.0f * p.x;
        s_py2[tid] = -2.0f * p.y;
        s_x2[tid]  = p.x * p.x + p.y * p.y;
    }
    __syncthreads();

    // Row constants for this warp's 4 rows (packed broadcasts)
    ull px2p[RPW], py2p[RPW], x2p[RPW];
    float rlo[RPW], rhi[RPW];
    const int r0 = w * RPW;
    #pragma unroll
    for (int r = 0; r < RPW; r++) {
        float a = s_px2[r0 + r]; px2p[r] = pk2(a, a);
        float c = s_py2[r0 + r]; py2p[r] = pk2(c, c);
        float e = s_x2[r0 + r];  x2p[r]  = pk2(e, e);
        rlo[r] = 3.4e38f; rhi[r] = 3.4e38f;
    }

    // Main sweep: 8 passes x 4 rows x 2 cols per lane
    #pragma unroll 1
    for (int pass = 0; pass < NPASS; pass++) {
        const int c = pass * 64 + lane * 2;
        ull gxp = *(const ull*)&s_gx[c];
        ull gyp = *(const ull*)&s_gy[c];
        ull g2p = *(const ull*)&s_g2[c];
        float clo = 3.4e38f, chi = 3.4e38f;
        #pragma unroll
        for (int r = 0; r < RPW; r++) {
            ull s = ffma2(px2p[r], gxp, g2p);      // -2px*gx + g2
            s = ffma2(py2p[r], gyp, s);            // += -2py*gy
            float lo, hi; upk2(s, lo, hi);
            rlo[r] = fminf(rlo[r], lo);            // row-min halves (excl x2)
            rhi[r] = fminf(rhi[r], hi);
            ull d = fadd2(s, x2p[r]);              // full distance
            float dlo, dhi; upk2(d, dlo, dhi);
            clo = fminf(clo, dlo);                 // col-min halves
            chi = fminf(chi, dhi);
        }
        // Exclusive per-warp column partial (no sync needed)
        *(float2*)&s_colpart[w][c] = make_float2(clo, chi);
    }

    // Row mins: combine halves + warp shuffle reduce (no barrier)
    #pragma unroll
    for (int r = 0; r < RPW; r++) {
        float x2lo, x2hi; upk2(x2p[r], x2lo, x2hi);
        float v = x2lo + fminf(rlo[r], rhi[r]);
        v = fminf(v, __shfl_xor_sync(0xFFFFFFFFu, v, 16));
        v = fminf(v, __shfl_xor_sync(0xFFFFFFFFu, v, 8));
        v = fminf(v, __shfl_xor_sync(0xFFFFFFFFu, v, 4));
        v = fminf(v, __shfl_xor_sync(0xFFFFFFFFu, v, 2));
        v = fminf(v, __shfl_xor_sync(0xFFFFFFFFu, v, 1));
        if (lane == 0)
            g_rpart[((size_t)cg * BATCH + b) * NPTS + (size_t)rt * RT + r0 + r] = v;
    }

    // Column combine across the 16 warps: one barrier, 1 col per thread
    __syncthreads();
    {
        float m = s_colpart[0][tid];
        #pragma unroll
        for (int k = 1; k < 16; k++) m = fminf(m, s_colpart[k][tid]);
        g_cpart[((size_t)rt * BATCH + b) * NPTS + (size_t)cg * CG + tid] = m;
    }
}

// ============================================================================
// Reduce 1: thread g finishes row entry (16-way) and col entry (128-way, 4
// independent accumulators for MLP), then block-sums both.
// ============================================================================
__global__ __launch_bounds__(256) void chamfer_reduce1() {
    const int t = threadIdx.x;
    const int g = blockIdx.x * 256 + t;   // 0..32767
    const size_t BN = (size_t)BATCH * NPTS;

    float r0 = 3.4e38f, r1 = 3.4e38f;
    #pragma unroll
    for (int k = 0; k < NCG; k += 2) {
        r0 = fminf(r0, g_rpart[(size_t)(k + 0) * BN + g]);
        r1 = fminf(r1, g_rpart[(size_t)(k + 1) * BN + g]);
    }
    float rm = fminf(r0, r1);

    float a0 = 3.4e38f, a1 = 3.4e38f, a2 = 3.4e38f, a3 = 3.4e38f;
    #pragma unroll 4
    for (int k = 0; k < NRT; k += 4) {
        a0 = fminf(a0, g_cpart[(size_t)(k + 0) * BN + g]);
        a1 = fminf(a1, g_cpart[(size_t)(k + 1) * BN + g]);
        a2 = fminf(a2, g_cpart[(size_t)(k + 2) * BN + g]);
        a3 = fminf(a3, g_cpart[(size_t)(k + 3) * BN + g]);
    }
    float cm = fminf(fminf(a0, a1), fminf(a2, a3));

    __shared__ float sr[256], sc[256];
    sr[t] = rm; sc[t] = cm;
    __syncthreads();
    for (int off = 128; off > 0; off >>= 1) {
        if (t < off) { sr[t] += sr[t + off]; sc[t] += sc[t + off]; }
        __syncthreads();
    }
    if (t == 0) { g_pr[blockIdx.x] = sr[0]; g_pc[blockIdx.x] = sc[0]; }
}

// ============================================================================
// Reduce 2: single block, fixed order -> deterministic.
// ============================================================================
__global__ void chamfer_reduce2(float* __restrict__ out) {
    __shared__ float sr[128], sc[128];
    const int t = threadIdx.x;   // 128 threads
    sr[t] = g_pr[t]; sc[t] = g_pc[t];
    __syncthreads();
    for (int off = 64; off > 0; off >>= 1) {
        if (t < off) { sr[t] += sr[t + off]; sc[t] += sc[t + off]; }
        __syncthreads();
    }
    if (t == 0) out[0] = (sr[0] + sc[0]) * (1.0f / (float)(BATCH * NPTS));
}

extern "C" void kernel_launch(void* const* d_in, const int* in_sizes, int n_in,
                              void* d_out, int out_size) {
    const float* pred = (const float*)d_in[0];
    const float* gt   = (const float*)d_in[1];

    dim3 grid(NCG, NRT, BATCH);          // 16 x 128 x 4 = 8192 blocks
    chamfer_tile<<<grid, 512>>>(pred, gt);
    chamfer_reduce1<<<128, 256>>>();
    chamfer_reduce2<<<1, 128>>>((float*)d_out);
}

// round 6
// speedup vs baseline: 1.2988x; 1.2988x over previous
#include <cuda_runtime.h>
#include <cstdint>

typedef unsigned long long ull;

#define BATCH 4
#define NPTS  8192
#define NTHR  128
#define Q     8                      // queries per thread (in registers)
#define QPB   (NTHR * Q)             // 1024 queries per block
#define QB    (NPTS / QPB)           // 8 query blocks
#define TT    512                    // targets per chunk (in shared)
#define TC    (NPTS / TT)            // 16 target chunks

// Scratch: partial row-mins per (dir, chunk). Disjoint writers, no atomics.
__device__ float g_minpart[2 * TC * BATCH * NPTS];   // 4 MB
__device__ float g_pa[128], g_pb[128];

// ---- packed f32x2 helpers (sm_100+) ----
__device__ __forceinline__ ull pk2(float lo, float hi) {
    ull r; asm("mov.b64 %0, {%1, %2};" : "=l"(r) : "f"(lo), "f"(hi)); return r;
}
__device__ __forceinline__ void upk2(ull v, float& lo, float& hi) {
    asm("mov.b64 {%0, %1}, %2;" : "=f"(lo), "=f"(hi) : "l"(v));
}
__device__ __forceinline__ ull ffma2(ull a, ull b, ull c) {
    ull d; asm("fma.rn.f32x2 %0, %1, %2, %3;" : "=l"(d) : "l"(a), "l"(b), "l"(c)); return d;
}

// ============================================================================
// One-directional NN pass. Block = (qb, tc, z) with z = dir*BATCH + b.
// dir 0: query=pred, target=gt.  dir 1: swapped.
// Each thread owns Q=8 queries; per-query min lives in registers -> no
// cross-thread reduction at all. Targets streamed from shared as f32x2 pairs:
//   s = fma(-2qy, ty, fma(-2qx, tx, t2))      (t2 = tx^2+ty^2, col constant)
//   rlo/rhi = fminf(...)                       (||q||^2 added once at the end)
// 2 FFMA2 + 2 FMNMX per 2 pairs. One barrier per block.
// ============================================================================
__global__ __launch_bounds__(NTHR, 7) void nn_pass(const float2* __restrict__ pred,
                                                   const float2* __restrict__ gt) {
    const int qb = blockIdx.x, tc = blockIdx.y, z = blockIdx.z;
    const int dir = z >> 2, b = z & 3;
    const int tid = threadIdx.x;

    const float2* __restrict__ qry = dir ? gt : pred;
    const float2* __restrict__ tgt = dir ? pred : gt;

    __shared__ __align__(16) float s_tx[TT], s_ty[TT], s_t2[TT];

    // Load target chunk (coalesced float2), derive t2 inline
    #pragma unroll
    for (int i = 0; i < TT / NTHR; i++) {
        int idx = tid + i * NTHR;
        float2 v = tgt[(size_t)b * NPTS + (size_t)tc * TT + idx];
        s_tx[idx] = v.x; s_ty[idx] = v.y; s_t2[idx] = v.x * v.x + v.y * v.y;
    }

    // Load this thread's 8 queries (coalesced), build packed broadcasts
    ull nqx[Q], nqy[Q];
    float qn2[Q], rlo[Q], rhi[Q];
    #pragma unroll
    for (int k = 0; k < Q; k++) {
        float2 p = qry[(size_t)b * NPTS + (size_t)qb * QPB + k * NTHR + tid];
        float ax = -2.0f * p.x, ay = -2.0f * p.y;
        nqx[k] = pk2(ax, ax);
        nqy[k] = pk2(ay, ay);
        qn2[k] = p.x * p.x + p.y * p.y;
        rlo[k] = 3.4e38f; rhi[k] = 3.4e38f;
    }
    __syncthreads();

    // Sweep 256 packed target pairs
    #pragma unroll 4
    for (int tp = 0; tp < TT / 2; tp++) {
        ull txp = *(const ull*)&s_tx[2 * tp];
        ull typ = *(const ull*)&s_ty[2 * tp];
        ull t2p = *(const ull*)&s_t2[2 * tp];
        #pragma unroll
        for (int k = 0; k < Q; k++) {
            ull s = ffma2(nqx[k], txp, t2p);   // -2qx*tx + t2
            s = ffma2(nqy[k], typ, s);         // += -2qy*ty
            float lo, hi; upk2(s, lo, hi);
            rlo[k] = fminf(rlo[k], lo);
            rhi[k] = fminf(rhi[k], hi);
        }
    }

    // Finalize: add ||q||^2, write partial min for this chunk (coalesced)
    #pragma unroll
    for (int k = 0; k < Q; k++) {
        float v = qn2[k] + fminf(rlo[k], rhi[k]);
        g_minpart[((size_t)(dir * TC + tc) * BATCH + b) * NPTS
                  + (size_t)qb * QPB + k * NTHR + tid] = v;
    }
}

// ============================================================================
// Reduce 1: thread g (= b*NPTS+n) finishes both directions' entries (min over
// 16 chunks each, 2 accumulators for MLP), then block-sums both.
// ============================================================================
__global__ __launch_bounds__(256) void chamfer_reduce1() {
    const int t = threadIdx.x;
    const int g = blockIdx.x * 256 + t;   // 0..32767
    const size_t BN = (size_t)BATCH * NPTS;

    float a0 = 3.4e38f, a1 = 3.4e38f, b0 = 3.4e38f, b1 = 3.4e38f;
    #pragma unroll
    for (int k = 0; k < TC; k += 2) {
        a0 = fminf(a0, g_minpart[(size_t)(k + 0) * BN + g]);
        a1 = fminf(a1, g_minpart[(size_t)(k + 1) * BN + g]);
        b0 = fminf(b0, g_minpart[(size_t)(TC + k + 0) * BN + g]);
        b1 = fminf(b1, g_minpart[(size_t)(TC + k + 1) * BN + g]);
    }
    float am = fminf(a0, a1), bm = fminf(b0, b1);

    __shared__ float sa[256], sb[256];
    sa[t] = am; sb[t] = bm;
    __syncthreads();
    for (int off = 128; off > 0; off >>= 1) {
        if (t < off) { sa[t] += sa[t + off]; sb[t] += sb[t + off]; }
        __syncthreads();
    }
    if (t == 0) { g_pa[blockIdx.x] = sa[0]; g_pb[blockIdx.x] = sb[0]; }
}

// ============================================================================
// Reduce 2: single block, fixed order -> deterministic.
// ============================================================================
__global__ void chamfer_reduce2(float* __restrict__ out) {
    __shared__ float sa[128], sb[128];
    const int t = threadIdx.x;   // 128 threads
    sa[t] = g_pa[t]; sb[t] = g_pb[t];
    __syncthreads();
    for (int off = 64; off > 0; off >>= 1) {
        if (t < off) { sa[t] += sa[t + off]; sb[t] += sb[t + off]; }
        __syncthreads();
    }
    if (t == 0) out[0] = (sa[0] + sb[0]) * (1.0f / (float)(BATCH * NPTS));
}

extern "C" void kernel_launch(void* const* d_in, const int* in_sizes, int n_in,
                              void* d_out, int out_size) {
    const float2* pred = (const float2*)d_in[0];
    const float2* gt   = (const float2*)d_in[1];

    dim3 grid(QB, TC, 2 * BATCH);        // 8 x 16 x 8 = 1024 blocks
    nn_pass<<<grid, NTHR>>>(pred, gt);
    chamfer_reduce1<<<128, 256>>>();
    chamfer_reduce2<<<1, 128>>>((float*)d_out);
}

// round 7
// speedup vs baseline: 1.3327x; 1.0261x over previous
#include <cuda_runtime.h>
#include <cstdint>

typedef unsigned long long ull;

#define BATCH 4
#define NPTS  8192
#define NTHR  128
#define Q     8                      // queries per thread (4 packed pairs)
#define QPB   (NTHR * Q)             // 1024 queries per block
#define QB    (NPTS / QPB)           // 8 query blocks
#define TT    512                    // targets per chunk (in shared)
#define TC    (NPTS / TT)            // 16 target chunks

// Scratch: partial row-mins per (dir, chunk). Disjoint writers, no atomics.
__device__ float g_minpart[2 * TC * BATCH * NPTS];   // 4 MB
__device__ float g_pa[128], g_pb[128];

// ---- packed f32x2 helpers (sm_100+) ----
__device__ __forceinline__ ull pk2(float lo, float hi) {
    ull r; asm("mov.b64 %0, {%1, %2};" : "=l"(r) : "f"(lo), "f"(hi)); return r;
}
__device__ __forceinline__ void upk2(ull v, float& lo, float& hi) {
    asm("mov.b64 {%0, %1}, %2;" : "=f"(lo), "=f"(hi) : "l"(v));
}
__device__ __forceinline__ ull ffma2(ull a, ull b, ull c) {
    ull d; asm("fma.rn.f32x2 %0, %1, %2, %3;" : "=l"(d) : "l"(a), "l"(b), "l"(c)); return d;
}

// ============================================================================
// One-directional NN pass. Block = (qb, tc, z) with z = dir*BATCH + b.
// dir 0: query=pred, target=gt.  dir 1: swapped.
// Queries packed 2-per-ull (distinct queries in lo/hi); targets stored in smem
// PRE-DOUBLED as (t,t) ulls so one LDS.64 yields a broadcast pair:
//   s = fma((-2q0x,-2q1x), (tx,tx), fma((-2q0y,-2q1y), (ty,ty), (t2,t2)))
//   -> (dist_q0, dist_q1) for this target; scalar mins per half.
// 2 FFMA2 + 2 FMNMX per 2 pairs; 3 broadcast LDS.64 per target (8 pairs).
// Per-query min lives in registers; one barrier per block; no cross-thread
// reduction. ~52 regs -> 32 warps/SM.
// ============================================================================
__global__ __launch_bounds__(NTHR, 8) void nn_pass(const float2* __restrict__ pred,
                                                   const float2* __restrict__ gt) {
    const int qb = blockIdx.x, tc = blockIdx.y, z = blockIdx.z;
    const int dir = z >> 2, b = z & 3;
    const int tid = threadIdx.x;

    const float2* __restrict__ qry = dir ? gt : pred;
    const float2* __restrict__ tgt = dir ? pred : gt;

    __shared__ __align__(16) ull s_txx[TT], s_tyy[TT], s_t22[TT];   // 12 KB

    // Load target chunk (coalesced float2), store doubled-broadcast ulls
    #pragma unroll
    for (int i = 0; i < TT / NTHR; i++) {
        int idx = tid + i * NTHR;
        float2 v = tgt[(size_t)b * NPTS + (size_t)tc * TT + idx];
        float n = v.x * v.x + v.y * v.y;
        s_txx[idx] = pk2(v.x, v.x);
        s_tyy[idx] = pk2(v.y, v.y);
        s_t22[idx] = pk2(n, n);
    }

    // Load this thread's 8 queries (coalesced), pack PAIRS of distinct queries
    ull qxp[Q / 2], qyp[Q / 2];
    float qn2[Q], rmin[Q];
    #pragma unroll
    for (int j = 0; j < Q / 2; j++) {
        float2 p0 = qry[(size_t)b * NPTS + (size_t)qb * QPB + (2 * j + 0) * NTHR + tid];
        float2 p1 = qry[(size_t)b * NPTS + (size_t)qb * QPB + (2 * j + 1) * NTHR + tid];
        qxp[j] = pk2(-2.0f * p0.x, -2.0f * p1.x);
        qyp[j] = pk2(-2.0f * p0.y, -2.0f * p1.y);
        qn2[2 * j + 0] = p0.x * p0.x + p0.y * p0.y;
        qn2[2 * j + 1] = p1.x * p1.x + p1.y * p1.y;
        rmin[2 * j + 0] = 3.4e38f;
        rmin[2 * j + 1] = 3.4e38f;
    }
    __syncthreads();

    // Sweep 512 targets; each yields distances for all 8 queries
    #pragma unroll 4
    for (int t = 0; t < TT; t++) {
        ull txx = s_txx[t];
        ull tyy = s_tyy[t];
        ull t22 = s_t22[t];
        #pragma unroll
        for (int j = 0; j < Q / 2; j++) {
            ull s = ffma2(qxp[j], txx, t22);   // -2qx*tx + t2  (both queries)
            s = ffma2(qyp[j], tyy, s);         // += -2qy*ty
            float lo, hi; upk2(s, lo, hi);
            rmin[2 * j + 0] = fminf(rmin[2 * j + 0], lo);
            rmin[2 * j + 1] = fminf(rmin[2 * j + 1], hi);
        }
    }

    // Finalize: add ||q||^2, write partial min for this chunk (coalesced)
    #pragma unroll
    for (int k = 0; k < Q; k++) {
        g_minpart[((size_t)(dir * TC + tc) * BATCH + b) * NPTS
                  + (size_t)qb * QPB + k * NTHR + tid] = qn2[k] + rmin[k];
    }
}

// ============================================================================
// Reduce 1: thread g (= b*NPTS+n) finishes both directions' entries (min over
// 16 chunks each, 2 accumulators for MLP), then block-sums both.
// ============================================================================
__global__ __launch_bounds__(256) void chamfer_reduce1() {
    const int t = threadIdx.x;
    const int g = blockIdx.x * 256 + t;   // 0..32767
    const size_t BN = (size_t)BATCH * NPTS;

    float a0 = 3.4e38f, a1 = 3.4e38f, b0 = 3.4e38f, b1 = 3.4e38f;
    #pragma unroll
    for (int k = 0; k < TC; k += 2) {
        a0 = fminf(a0, g_minpart[(size_t)(k + 0) * BN + g]);
        a1 = fminf(a1, g_minpart[(size_t)(k + 1) * BN + g]);
        b0 = fminf(b0, g_minpart[(size_t)(TC + k + 0) * BN + g]);
        b1 = fminf(b1, g_minpart[(size_t)(TC + k + 1) * BN + g]);
    }
    float am = fminf(a0, a1), bm = fminf(b0, b1);

    __shared__ float sa[256], sb[256];
    sa[t] = am; sb[t] = bm;
    __syncthreads();
    for (int off = 128; off > 0; off >>= 1) {
        if (t < off) { sa[t] += sa[t + off]; sb[t] += sb[t + off]; }
        __syncthreads();
    }
    if (t == 0) { g_pa[blockIdx.x] = sa[0]; g_pb[blockIdx.x] = sb[0]; }
}

// ============================================================================
// Reduce 2: single block, fixed order -> deterministic.
// ============================================================================
__global__ void chamfer_reduce2(float* __restrict__ out) {
    __shared__ float sa[128], sb[128];
    const int t = threadIdx.x;   // 128 threads
    sa[t] = g_pa[t]; sb[t] = g_pb[t];
    __syncthreads();
    for (int off = 64; off > 0; off >>= 1) {
        if (t < off) { sa[t] += sa[t + off]; sb[t] += sb[t + off]; }
        __syncthreads();
    }
    if (t == 0) out[0] = (sa[0] + sb[0]) * (1.0f / (float)(BATCH * NPTS));
}

extern "C" void kernel_launch(void* const* d_in, const int* in_sizes, int n_in,
                              void* d_out, int out_size) {
    const float2* pred = (const float2*)d_in[0];
    const float2* gt   = (const float2*)d_in[1];

    dim3 grid(QB, TC, 2 * BATCH);        // 8 x 16 x 8 = 1024 blocks
    nn_pass<<<grid, NTHR>>>(pred, gt);
    chamfer_reduce1<<<128, 256>>>();
    chamfer_reduce2<<<1, 128>>>((float*)d_out);
}